// round 3
// baseline (speedup 1.0000x reference)
#include <cuda_runtime.h>
#include <math.h>

#define EPSV  1e-20f
#define L2EPS -66.438561897f
#define Hh 192
#define Ww 192
#define HW (Hh*Ww)

__device__ float g_wcd[1024];     // channel_d [o][i] normalized
__device__ float g_wsd[288];      // spatial_d [i][k] normalized
__device__ float g_wce[1024];     // channel_e [o][i] normalized
__device__ float g_wdir[512];     // [p][i][d] normalized over d
__device__ float g_wse[1152];     // [i][d][k] normalized over k
__device__ float g_wprop[128];    // [i][d]
__device__ float g_wpow0[128];    // [i][d]
__device__ float g_wpow1[128];    // [i][d]
__device__ float g_cein [2*32*4*HW];
__device__ float g_ecein[2*32*4*HW];

__device__ __forceinline__ float sp_(float v){ return log1pf(expf(v)); }
__device__ __forceinline__ float sig_(float v){ return 1.f/(1.f+expf(-v)); }
__device__ __forceinline__ float ex2_(float v){
    float r; asm("ex2.approx.f32 %0, %1;" : "=f"(r) : "f"(v)); return r;
}

__global__ void prep_kernel(const float* __restrict__ Wcd, const float* __restrict__ Wsd,
                            const float* __restrict__ Wce, const float* __restrict__ Wse0,
                            const float* __restrict__ Wse1, const float* __restrict__ Wse3,
                            const float* __restrict__ Wdir, const float* __restrict__ Wpow,
                            const float* __restrict__ Wprop)
{
    int t = threadIdx.x;
    if (t >= 32) return;
    { // channel_d row o=t
        float s=0.f; for(int i=0;i<32;i++) s+=sp_(Wcd[t*32+i]);
        float inv=1.f/s; for(int i=0;i<32;i++) g_wcd[t*32+i]=sp_(Wcd[t*32+i])*inv;
    }
    { // channel_e row o=t
        float s=0.f; for(int i=0;i<32;i++) s+=sp_(Wce[t*32+i]);
        float inv=1.f/s; for(int i=0;i<32;i++) g_wce[t*32+i]=sp_(Wce[t*32+i])*inv;
    }
    { // spatial_d i=t: rows [a,b,a], normalize over 9
        float v[9]; float s=0.f;
        for(int h=0;h<3;h++){
            float a=sp_(Wsd[t*6+h*2+0]), b=sp_(Wsd[t*6+h*2+1]);
            v[h*3+0]=a; v[h*3+1]=b; v[h*3+2]=a;
        }
        for(int k=0;k<9;k++) s+=v[k];
        float inv=1.f/s; for(int k=0;k<9;k++) g_wsd[t*9+k]=v[k]*inv;
    }
    { // dir weights i=t, normalized over d
        float d[10]; for(int j=0;j<10;j++) d[j]=sp_(Wdir[t*10+j]);
        float rows[4][4]={{d[0],d[1],d[2],d[3]},{d[4],d[5],d[4],d[6]},
                          {d[2],d[1],d[0],d[3]},{d[7],d[8],d[7],d[9]}};
        for(int p=0;p<4;p++){
            float s=rows[p][0]+rows[p][1]+rows[p][2]+rows[p][3];
            float inv=1.f/s;
            for(int dd=0;dd<4;dd++) g_wdir[(p*32+t)*4+dd]=rows[p][dd]*inv;
        }
    }
    { // spatial_e i=t: d0=se0, d1=[a,b,a], d2=rev(se0), d3=[a,b,a], norm per d
        float se0[9],se1v[9],se3v[9],se2[9];
        for(int k=0;k<9;k++) se0[k]=sp_(Wse0[t*9+k]);
        for(int h=0;h<3;h++){
            float a=sp_(Wse1[t*6+h*2+0]), b=sp_(Wse1[t*6+h*2+1]);
            se1v[h*3+0]=a; se1v[h*3+1]=b; se1v[h*3+2]=a;
            float a3=sp_(Wse3[t*6+h*2+0]), b3=sp_(Wse3[t*6+h*2+1]);
            se3v[h*3+0]=a3; se3v[h*3+1]=b3; se3v[h*3+2]=a3;
            se2[h*3+0]=se0[h*3+2]; se2[h*3+1]=se0[h*3+1]; se2[h*3+2]=se0[h*3+0];
        }
        const float* arr[4]={se0,se1v,se2,se3v};
        for(int dd=0;dd<4;dd++){
            float s=0.f; for(int k=0;k<9;k++) s+=arr[dd][k];
            float inv=1.f/s;
            for(int k=0;k<9;k++) g_wse[(t*4+dd)*9+k]=arr[dd][k]*inv;
        }
    }
    { // prop [s1,s0,s1,s2]; pow0=[p0,p2,p1,p4], pow1=[p1,p3,p0,p4]
        float s0=sig_(Wprop[t*3+0]), s1=sig_(Wprop[t*3+1]), s2=sig_(Wprop[t*3+2]);
        g_wprop[t*4+0]=s1; g_wprop[t*4+1]=s0; g_wprop[t*4+2]=s1; g_wprop[t*4+3]=s2;
        float p0=sp_(Wpow[t*5+0]),p1=sp_(Wpow[t*5+1]),p2=sp_(Wpow[t*5+2]),
              p3=sp_(Wpow[t*5+3]),p4=sp_(Wpow[t*5+4]);
        g_wpow0[t*4+0]=p0; g_wpow0[t*4+1]=p2; g_wpow0[t*4+2]=p1; g_wpow0[t*4+3]=p4;
        g_wpow1[t*4+0]=p1; g_wpow1[t*4+1]=p3; g_wpow1[t*4+2]=p0; g_wpow1[t*4+3]=p4;
    }
}

// K1: build ce_in / ece_in (log-space powers, no divides)
__global__ void __launch_bounds__(256) k1_prepin(const float* __restrict__ x,
                                                 const float* __restrict__ ece,
                                                 const float* __restrict__ ce)
{
    int plane = blockIdx.y;                 // b*32+i, 0..63
    int i = plane & 31;
    int pix = blockIdx.x*256 + threadIdx.x; // 144*256 = 36864 exact
    int y = pix/Ww, xx = pix - y*Ww;
    const float* dcd = x + (size_t)plane*HW;
    const float* cd  = x + (size_t)(64+plane)*HW;

    float lv[8], cv[8];
    const int dy[8]={-1,-1,-1,0,0,1,1,1};
    const int dxv[8]={-1,0,1,-1,1,-1,0,1};
#pragma unroll
    for(int k=0;k<8;k++){
        int yy=y+dy[k], xk=xx+dxv[k];
        bool ok=((unsigned)yy<(unsigned)Hh)&&((unsigned)xk<(unsigned)Ww);
        float c=0.f,dc=0.f;
        if(ok){ int off=yy*Ww+xk; c=cd[off]; dc=dcd[off]; }
        cv[k]=c;
        float l=__log2f(dc)-__log2f(c+EPSV);   // log2(dcd/(cd+EPS))
        if(!ok||dc<=0.f) l=-1e30f;             // pad -> d=0
        lv[k]=l;
    }
    const int Ai[4]={0,1,2,4};   // (-1,-1),(-1,0),(-1,1),(0,1)
    const int Bi[4]={7,6,5,3};   // (1,1),(1,0),(1,-1),(0,-1)
    size_t base=(size_t)plane*4*HW + pix;
#pragma unroll
    for(int d=0;d<4;d++){
        float lA=lv[Ai[d]], lB=lv[Bi[d]];
        float la=fminf(fmaxf(lA-fmaxf(lB,L2EPS),L2EPS),0.f);
        float lb=fminf(fmaxf(lB-fmaxf(lA,L2EPS),L2EPS),0.f);
        float en=ex2_(fminf(g_wpow0[i*4+d]*la, g_wpow1[i*4+d]*lb));
        float cn=cv[Ai[d]]*cv[Bi[d]];
        float wp=g_wprop[i*4+d];
        size_t off=base+(size_t)d*HW;
        g_cein [off]=ce [off]*wp+cn*(1.f-wp);
        g_ecein[off]=ece[off]*wp+en*cn*(1.f-wp);
    }
}

// K2: factorized conv_e: depthwise 3x3 -> 4x4 dir mix -> 32x32 channel mix
__global__ void __launch_bounds__(256) k2_conve(float* __restrict__ dout)
{
    __shared__ float4 sh4[64][33];      // [pix][i], float4 over p
    __shared__ float sh_wse[1152];
    __shared__ float sh_wdir[512];
    __shared__ float sh_wceT[1024];     // [ii][o]
    int tid=threadIdx.x;
    for(int k=tid;k<1152;k+=256) sh_wse[k]=g_wse[k];
    for(int k=tid;k<512;k+=256)  sh_wdir[k]=g_wdir[k];
    for(int k=tid;k<1024;k+=256) sh_wceT[k]=g_wce[(k&31)*32+(k>>5)];
    int t=blockIdx.x;
    int b=t/576; int rem=t-b*576;
    int y0=rem/3; int x0=(rem-y0*3)*64;
    int i=tid>>3, px8=tid&7;
    int xb=x0+px8*8;
    int o=tid&31, pg=tid>>5;
    __syncthreads();

    const size_t ece_off=(size_t)128*HW;
    const size_t ceo_off=(size_t)384*HW;

    for(int sel=0;sel<2;sel++){
        const float* __restrict__ in = sel ? g_ecein : g_cein;
        float tacc[4][8];
#pragma unroll
        for(int p=0;p<4;p++)
#pragma unroll
            for(int j=0;j<8;j++) tacc[p][j]=0.f;
#pragma unroll
        for(int d=0;d<4;d++){
            const float* ch = in + (size_t)((b*32+i)*4+d)*HW;
            const float* w = sh_wse + (i*4+d)*9;
            float s[8];
#pragma unroll
            for(int j=0;j<8;j++) s[j]=0.f;
#pragma unroll
            for(int ry=0;ry<3;ry++){
                int yy=y0+ry-1;
                bool yok=((unsigned)yy<(unsigned)Hh);
                const float* rp=ch+yy*Ww;
                float r[16];
#pragma unroll
                for(int seg=0;seg<4;seg++){
                    int xs=xb-4+seg*4;    // aligned; fully in or out
                    float4 v=make_float4(0.f,0.f,0.f,0.f);
                    if(yok&&(unsigned)xs<(unsigned)Ww)
                        v=*reinterpret_cast<const float4*>(rp+xs);
                    r[seg*4]=v.x; r[seg*4+1]=v.y; r[seg*4+2]=v.z; r[seg*4+3]=v.w;
                }
                float w0=w[ry*3],w1=w[ry*3+1],w2=w[ry*3+2];
#pragma unroll
                for(int j=0;j<8;j++)
                    s[j]+=w0*r[j+3]+w1*r[j+4]+w2*r[j+5];
            }
#pragma unroll
            for(int p=0;p<4;p++){
                float wd=sh_wdir[(p*32+i)*4+d];
#pragma unroll
                for(int j=0;j<8;j++) tacc[p][j]+=wd*s[j];
            }
        }
#pragma unroll
        for(int j=0;j<8;j++)
            sh4[px8*8+j][i]=make_float4(tacc[0][j],tacc[1][j],tacc[2][j],tacc[3][j]);
        __syncthreads();

        // channel mix: o = tid&31, broadcast smem reads
        float acc[4][8];
#pragma unroll
        for(int p=0;p<4;p++)
#pragma unroll
            for(int j=0;j<8;j++) acc[p][j]=0.f;
#pragma unroll 4
        for(int ii=0;ii<32;ii++){
            float wv=sh_wceT[ii*32+o];
#pragma unroll
            for(int j=0;j<8;j++){
                float4 tv=sh4[pg*8+j][ii];
                acc[0][j]+=wv*tv.x; acc[1][j]+=wv*tv.y;
                acc[2][j]+=wv*tv.z; acc[3][j]+=wv*tv.w;
            }
        }
        size_t ooff = sel ? ece_off : ceo_off;  // sel0->ce_out, sel1->ece_out
#pragma unroll
        for(int p=0;p<4;p++){
            float* op=dout+ooff+(size_t)((b*32+o)*4+p)*HW+y0*Ww+x0+pg*8;
            *reinterpret_cast<float4*>(op)  =make_float4(acc[p][0],acc[p][1],acc[p][2],acc[p][3]);
            *reinterpret_cast<float4*>(op+4)=make_float4(acc[p][4],acc[p][5],acc[p][6],acc[p][7]);
        }
        __syncthreads();
    }
}

// K3: e9-modulated depthwise + 32x32 mix -> main output
__global__ void __launch_bounds__(256) k3_final(const float* __restrict__ x,
                                                float* __restrict__ dout)
{
    __shared__ float shd[64][33];
    __shared__ float shc[64][33];
    __shared__ float sh_wcdT[1024];   // [ii][o]
    __shared__ float sh_wsd[288];
    int tid=threadIdx.x;
    for(int k=tid;k<1024;k+=256) sh_wcdT[k]=g_wcd[(k&31)*32+(k>>5)];
    for(int k=tid;k<288;k+=256)  sh_wsd[k]=g_wsd[k];
    int t=blockIdx.x;
    int b=t/576; int rem=t-b*576;
    int y0=rem/3; int x0=(rem-y0*3)*64;
    int i=tid>>3, px8=tid&7;
    int xb=x0+px8*8;
    int o=tid&31, pg=tid>>5;
    __syncthreads();

    const size_t ece_off=(size_t)128*HW;
    const size_t ceo_off=(size_t)384*HW;
    float e[5][8];
#pragma unroll
    for(int j=0;j<8;j++) e[4][j]=1.f;
    size_t pbase=(size_t)(b*32+i)*4*HW + y0*Ww + xb;
#pragma unroll
    for(int d=0;d<4;d++){
        const float* pe=dout+ece_off+pbase+(size_t)d*HW;
        const float* pc=dout+ceo_off+pbase+(size_t)d*HW;
#pragma unroll
        for(int j=0;j<8;j+=4){
            float4 ev=*reinterpret_cast<const float4*>(pe+j);
            float4 c4=*reinterpret_cast<const float4*>(pc+j);
            e[d][j]  =fminf(fmaxf(__fdividef(ev.x,c4.x+EPSV),EPSV),1.f);
            e[d][j+1]=fminf(fmaxf(__fdividef(ev.y,c4.y+EPSV),EPSV),1.f);
            e[d][j+2]=fminf(fmaxf(__fdividef(ev.z,c4.z+EPSV),EPSV),1.f);
            e[d][j+3]=fminf(fmaxf(__fdividef(ev.w,c4.w+EPSV),EPSV),1.f);
        }
    }
    const float* dcd=x+(size_t)(b*32+i)*HW;
    const float* cdp=x+(size_t)(64+b*32+i)*HW;
    const float* w=sh_wsd+i*9;
    float md[8],mc[8];
#pragma unroll
    for(int j=0;j<8;j++){ md[j]=0.f; mc[j]=0.f; }
    const int emap[9]={0,1,2,3,4,3,2,1,0};
#pragma unroll
    for(int ry=0;ry<3;ry++){
        int yy=y0+ry-1;
        bool yok=((unsigned)yy<(unsigned)Hh);
        const float* rpd=dcd+yy*Ww;
        const float* rpc=cdp+yy*Ww;
        float rd[16],rc[16];
#pragma unroll
        for(int seg=0;seg<4;seg++){
            int xs=xb-4+seg*4;
            float4 vd=make_float4(0.f,0.f,0.f,0.f), vc=vd;
            if(yok&&(unsigned)xs<(unsigned)Ww){
                vd=*reinterpret_cast<const float4*>(rpd+xs);
                vc=*reinterpret_cast<const float4*>(rpc+xs);
            }
            rd[seg*4]=vd.x; rd[seg*4+1]=vd.y; rd[seg*4+2]=vd.z; rd[seg*4+3]=vd.w;
            rc[seg*4]=vc.x; rc[seg*4+1]=vc.y; rc[seg*4+2]=vc.z; rc[seg*4+3]=vc.w;
        }
#pragma unroll
        for(int rx=0;rx<3;rx++){
            int k=ry*3+rx;
            float wk=w[k];
#pragma unroll
            for(int j=0;j<8;j++){
                float f=wk*e[emap[k]][j];
                md[j]+=f*rd[j+3+rx];
                mc[j]+=f*rc[j+3+rx];
            }
        }
    }
#pragma unroll
    for(int j=0;j<8;j++){ shd[px8*8+j][i]=md[j]; shc[px8*8+j][i]=mc[j]; }
    __syncthreads();
    float ad[8],ac[8];
#pragma unroll
    for(int j=0;j<8;j++){ ad[j]=0.f; ac[j]=0.f; }
#pragma unroll 4
    for(int ii=0;ii<32;ii++){
        float wv=sh_wcdT[ii*32+o];
#pragma unroll
        for(int j=0;j<8;j++){
            ad[j]+=wv*shd[pg*8+j][ii];
            ac[j]+=wv*shc[pg*8+j][ii];
        }
    }
    float* od=dout+(size_t)(b*32+o)*HW+y0*Ww+x0+pg*8;
    float* oc=dout+(size_t)(64+b*32+o)*HW+y0*Ww+x0+pg*8;
    *reinterpret_cast<float4*>(od)  =make_float4(ad[0],ad[1],ad[2],ad[3]);
    *reinterpret_cast<float4*>(od+4)=make_float4(ad[4],ad[5],ad[6],ad[7]);
    *reinterpret_cast<float4*>(oc)  =make_float4(ac[0],ac[1],ac[2],ac[3]);
    *reinterpret_cast<float4*>(oc+4)=make_float4(ac[4],ac[5],ac[6],ac[7]);
}

extern "C" void kernel_launch(void* const* d_in, const int* in_sizes, int n_in,
                              void* d_out, int out_size)
{
    const float* x   =(const float*)d_in[0];
    const float* ece =(const float*)d_in[1];
    const float* ce  =(const float*)d_in[2];
    prep_kernel<<<1,32>>>((const float*)d_in[3],(const float*)d_in[4],
                          (const float*)d_in[5],(const float*)d_in[6],
                          (const float*)d_in[7],(const float*)d_in[8],
                          (const float*)d_in[9],(const float*)d_in[10],
                          (const float*)d_in[11]);
    k1_prepin<<<dim3(144,64),256>>>(x,ece,ce);
    k2_conve<<<1152,256>>>((float*)d_out);
    k3_final<<<1152,256>>>(x,(float*)d_out);
}